// round 17
// baseline (speedup 1.0000x reference)
#include <cuda_runtime.h>
#include <cuda_bf16.h>
#include <cstdint>

// MoE gate: logits = x[N,1024] @ W[4,1024]^T in exact fp32, softmax with
// FTZ-exp emulation, top-2 with lowest-index tie-break on flushed (zero)
// scores. Output (fp32): [ topk_idx (N*2) | topk_weight (N*2) | aux_loss(1) ]
// aux_loss == 0.01 analytically.
//
// R17: R16 (warp-autonomous cp.async + weights in registers) with a finer,
// deeper pipeline: tile = 1 row (4KB), 6-slot per-warp ring, wait_group 5
// -> 5 tiles (20KB) in flight per warp and 2x finer wait release.
// Per-scalar accumulation order identical to R5..R16 (canary 1.032705e-06).

constexpr int H        = 1024;
constexpr int E        = 4;
constexpr int THREADS  = 256;
constexpr int WARPS    = THREADS / 32;     // 8
constexpr int GROUP_ROWS = WARPS;          // 8 rows per block-iteration (1/warp)
constexpr int SLOTS    = 6;                // per-warp ring depth
constexpr int TILE_F4  = H / 4;            // 256 float4 = 4KB (one row)
constexpr int SMEM_BYTES = (WARPS * SLOTS * TILE_F4) * 16;  // 192KB
constexpr int GRID     = 148;              // 1 block/SM, persistent

#define EXP_FLUSH_T (-87.336544f)

__device__ __forceinline__ uint32_t s2u(const void* p) {
    return (uint32_t)__cvta_generic_to_shared(p);
}

__global__ __launch_bounds__(THREADS, 1)
void moe_gate_kernel(const float* __restrict__ x,
                     const float* __restrict__ w,
                     float* __restrict__ out, int n, int ngroups)
{
    extern __shared__ float4 smem[];
    float4* xs = smem;                       // 8 x 6 x 4KB warp rings

    const int tid  = threadIdx.x;
    const int lane = tid & 31;
    const int wid  = tid >> 5;

    const int my_ngroups = (blockIdx.x < ngroups)
                         ? ((ngroups - 1 - blockIdx.x) / GRID + 1) : 0;

    float4* ring = xs + wid * SLOTS * TILE_F4;

    // Issue this warp's tile for group-index g: 1 contiguous row (4KB).
    // Unconditional commit keeps wait_group counting uniform at the tail.
    auto issue = [&](int g) {
        if (g < my_ngroups) {
            int row = (blockIdx.x + g * GRID) * GROUP_ROWS + wid;
            if (row >= n) row = n - 1;              // safety clamp
            const float4* src =
                reinterpret_cast<const float4*>(x) + (size_t)row * TILE_F4;
            float4* dst = ring + (g % SLOTS) * TILE_F4;
            #pragma unroll
            for (int i = 0; i < TILE_F4 / 32; i++) {   // 8 per lane
                const int idx = i * 32 + lane;          // 512B coalesced/instr
                asm volatile("cp.async.cg.shared.global [%0], [%1], 16;"
                             :: "r"(s2u(dst + idx)), "l"(src + idx));
            }
        }
        asm volatile("cp.async.commit_group;");
    };

    // Prologue: fill 5 of 6 slots.
    issue(0); issue(1); issue(2); issue(3); issue(4);

    // Per-lane weight registers: lane's float4-columns are c*32+lane,
    // c = 0..7, for each of the 4 experts. 32 float4 = 128 regs.
    float4 wreg[E][8];
    #pragma unroll
    for (int e = 0; e < E; e++)
        #pragma unroll
        for (int c = 0; c < 8; c++)
            wreg[e][c] = reinterpret_cast<const float4*>(w)
                             [e * (H / 4) + c * 32 + lane];

    if (blockIdx.x == 0 && tid == 0)
        out[4 * (size_t)n] = 0.01f;    // aux = 0.25*4*0.01 (analytic)

    for (int g = 0; g < my_ngroups; g++) {
        issue(g + 5);                              // slot (g+5)%6 == (g-1)%6
        asm volatile("cp.async.wait_group 5;" ::: "memory");  // tile g ready

        const float4* xb = ring + (g % SLOTS) * TILE_F4;

        float acc[E];
        #pragma unroll
        for (int e = 0; e < E; e++) acc[e] = 0.0f;

        #pragma unroll
        for (int c = 0; c < 8; c++) {              // 8 chunks, same as R5
            const int ci = c * 32 + lane;
            const float4 xv = xb[ci];
            #pragma unroll
            for (int e = 0; e < E; e++) {
                const float4 wv = wreg[e][c];
                acc[e] += xv.x * wv.x;
                acc[e] += xv.y * wv.y;
                acc[e] += xv.z * wv.z;
                acc[e] += xv.w * wv.w;
            }
        }

        // Warp butterfly reduce (identical order to R5 row 0).
        #pragma unroll
        for (int off = 16; off > 0; off >>= 1)
            #pragma unroll
            for (int e = 0; e < E; e++)
                acc[e] += __shfl_xor_sync(0xffffffffu, acc[e], off);

        // Lane 0 finishes this warp's row (identical epilogue).
        int row = (blockIdx.x + g * GRID) * GROUP_ROWS + wid;
        if (row >= n) row = n - 1;
        if (lane == 0) {
            float l[E];
            #pragma unroll
            for (int e = 0; e < E; e++) l[e] = acc[e];

            const float m = fmaxf(fmaxf(l[0], l[1]), fmaxf(l[2], l[3]));
            float p2[E];
            float s = 0.0f;
            #pragma unroll
            for (int e = 0; e < E; e++) {
                const float aa = l[e] - m;
                p2[e] = (aa <= EXP_FLUSH_T) ? 0.0f : expf(aa);
                s += p2[e];
            }
            int i1 = 0; float b1 = p2[0];
            #pragma unroll
            for (int e = 1; e < E; e++)
                if (p2[e] > b1) { b1 = p2[e]; i1 = e; }
            int i2 = -1; float b2 = -1.0f;
            #pragma unroll
            for (int e = 0; e < E; e++)
                if (e != i1 && p2[e] > b2) { b2 = p2[e]; i2 = e; }

            const float inv = 1.0f / s;
            reinterpret_cast<float2*>(out)[row] =
                make_float2((float)i1, (float)i2);
            reinterpret_cast<float2*>(out + 2 * (size_t)n)[row] =
                make_float2(b1 * inv, b2 * inv);
        }
    }
}

extern "C" void kernel_launch(void* const* d_in, const int* in_sizes, int n_in,
                              void* d_out, int out_size)
{
    const float* x = (const float*)d_in[0];
    const float* w = (const float*)d_in[1];
    float* out = (float*)d_out;

    const int h = in_sizes[1] / E;                         // 1024
    const int n = in_sizes[0] / h;                         // 32768 rows
    const int ngroups = (n + GROUP_ROWS - 1) / GROUP_ROWS; // 4096
    (void)n_in; (void)out_size;

    static bool attr_done = false;
    if (!attr_done) {
        cudaFuncSetAttribute(moe_gate_kernel,
                             cudaFuncAttributeMaxDynamicSharedMemorySize,
                             SMEM_BYTES);
        attr_done = true;
    }

    moe_gate_kernel<<<GRID, THREADS, SMEM_BYTES>>>(x, w, out, n, ngroups);
}